// round 10
// baseline (speedup 1.0000x reference)
#include <cuda_runtime.h>
#include <cuda_fp16.h>

// SparseConv1dNeq: fake-quant(in) -> masked sparse conv1d (fan-in 8, pad 1) -> fake-quant(out)
// x [512,64,1024] f32, weight [64,64,3] f32, mask [64,64,3] f32, out [512,64,1024] f32
//
// int8 smem design: quantized x is exactly int8. Store biased-uint8 in THREE
// byte-shifted copies (A:k=1, B:k=0, C:k=2), 8KB each. A tap read is one
// LDS.32 (32 lanes x 4B contiguous = 1 wavefront per 128 positions).
// Decode: f = bits(0x4B000000|u) - 8388736.0f == q exactly (integer-in-fp32).
// IN_SCALE folded into weights at prep. Output math identical to fp32 reference
// modulo sum order (same as prior rounds).

#define BATCH   512
#define IN_CH   64
#define OUT_CH  64
#define KW      3
#define LEN     1024
#define FAN_IN  8
#define TILE_T  128
#define NTHREADS 256

#define ROW_B  128             // bytes per row per copy
#define A_BASE 0               // A[r][j] = x[t0+j]    (k=1)
#define B_BASE 8192            // B[r][j] = x[t0-1+j]  (k=0)
#define C_BASE 16384           // C[r][j] = x[t0+1+j]  (k=2)
#define SMEM_BYTES 24576

#define IN_SCALE      0.0625f
#define OUT_SCALE     0.125f
#define OUT_SCALE_INV 8.0f

// Packed taps: per out channel 4 x uint4 = {byteOff0, w0bits, byteOff1, w1bits}
__device__ uint4 g_tap[OUT_CH * FAN_IN / 2];

// ---------------- Prep: parallel ballot-based tap compaction ----------------
__global__ void prep_taps_kernel(const float* __restrict__ weight,
                                 const float* __restrict__ mask) {
    const int o   = blockIdx.x;
    const int idx = threadIdx.x;          // 0..191 over (ic*KW + k)
    __shared__ int wcnt[6];
    __shared__ int total;

    float m = mask[o * (IN_CH * KW) + idx];
    bool  p = (m != 0.0f);

    unsigned bal = __ballot_sync(0xffffffffu, p);
    int warp = idx >> 5;
    int lane = idx & 31;
    if (lane == 0) wcnt[warp] = __popc(bal);
    __syncthreads();

    int prefix = 0;
    #pragma unroll
    for (int w = 0; w < 6; w++)
        if (w < warp) prefix += wcnt[w];
    if (idx == 0) {
        int t = 0;
        #pragma unroll
        for (int w = 0; w < 6; w++) t += wcnt[w];
        total = t;
    }
    int rank = prefix + __popc(bal & ((1u << lane) - 1u));
    __syncthreads();

    int* gt = (int*)g_tap;
    if (p && rank < FAN_IN) {
        int ic = idx / KW;
        int k  = idx - ic * KW;
        int off;
        if (k == 0)      off = B_BASE + ic * ROW_B;
        else if (k == 1) off = A_BASE + ic * ROW_B;
        else             off = C_BASE + ic * ROW_B;
        gt[(o * FAN_IN + rank) * 2]     = off;
        // fold IN_SCALE into the weight: tap operates on integer q
        gt[(o * FAN_IN + rank) * 2 + 1] = __float_as_int(weight[o * (IN_CH * KW) + idx] * m * IN_SCALE);
    }
    if (idx < FAN_IN && idx >= total) {
        gt[(o * FAN_IN + idx) * 2]     = 0;
        gt[(o * FAN_IN + idx) * 2 + 1] = 0;
    }
}

// biased quant: u = clip(rint(x*16)+128, 0, 255)  (rint(y)+128 == rint(y+128))
__device__ __forceinline__ unsigned bq(float x) {
    return (unsigned)fminf(fmaxf(rintf(fmaf(x, 16.0f, 128.0f)), 0.0f), 255.0f);
}
__device__ __forceinline__ float fq_out(float v) {
    return fminf(fmaxf(rintf(v * OUT_SCALE_INV), -128.0f), 127.0f) * OUT_SCALE;
}
// decode byte i of packed word -> float q (exact)
__device__ __forceinline__ float u2f(unsigned w, int i) {
    return __uint_as_float(__byte_perm(w, 0x4B000000u, 0x7650u + (unsigned)i)) - 8388736.0f;
}

// ---------------- Main kernel ----------------
__global__ __launch_bounds__(NTHREADS, 5)
void sparse_conv1d_kernel(const float* __restrict__ x,
                          float* __restrict__ out) {
    __shared__ __align__(16) char xs[SMEM_BYTES];
    char* sp = xs;

    const int blk  = blockIdx.x;
    const int n    = blk >> 3;
    const int tile = blk & 7;
    const int t0   = tile * TILE_T;

    const float* xn = x + (size_t)n * IN_CH * LEN;
    const int tid  = threadIdx.x;
    const int lane = tid & 31;
    const int warp = tid >> 5;

    // ---- Load: warp covers one row per iter (32 lanes x 4 positions) ----
    #pragma unroll
    for (int it = 0; it < 8; it++) {
        const int r = warp + it * 8;
        const float* rowg = xn + r * LEN;
        const float4 q = __ldcs(reinterpret_cast<const float4*>(rowg + t0 + (lane << 2)));

        unsigned w = bq(q.x) | (bq(q.y) << 8) | (bq(q.z) << 16) | (bq(q.w) << 24);

        // halo: lane 0 -> x[t0-1], lane 31 -> x[t0+128] (biased-zero 128 when OOB)
        bool hl = (lane == 0)  && (t0 > 0);
        bool hr = (lane == 31) && (t0 + TILE_T < LEN);
        unsigned hu = 128u;
        if (hl) hu = bq(__ldcs(rowg + t0 - 1));
        if (hr) hu = bq(__ldcs(rowg + t0 + TILE_T));

        unsigned w_prev = __shfl_up_sync(0xffffffffu, w, 1);
        unsigned w_next = __shfl_down_sync(0xffffffffu, w, 1);
        if (lane == 0)  w_prev = hu << 24;   // byte3 = x[t0-1]
        if (lane == 31) w_next = hu;         // byte0 = x[t0+128]

        char* rp = sp + r * ROW_B + (lane << 2);
        *reinterpret_cast<unsigned*>(rp + A_BASE) = w;
        // B word = (x[4l-1], x[4l], x[4l+1], x[4l+2]) = (prev.b3, w.b0, w.b1, w.b2)
        *reinterpret_cast<unsigned*>(rp + B_BASE) = __byte_perm(w, w_prev, 0x2107);
        // C word = (x[4l+1], x[4l+2], x[4l+3], x[4l+4]) = (w.b1, w.b2, w.b3, next.b0)
        *reinterpret_cast<unsigned*>(rp + C_BASE) = __byte_perm(w, w_next, 0x4321);
    }
    __syncthreads();

    // ---- Compute: warp w -> out channels [w*8, w*8+8); lane -> positions 4l..4l+3 ----
    float* outn = out + (size_t)n * OUT_CH * LEN + t0;
    const int lb = lane << 2;

    #pragma unroll 1
    for (int oi = 0; oi < 8; oi++) {
        const int o = warp * 8 + oi;
        const uint4* taps = g_tap + o * (FAN_IN / 2);

        float a0 = 0.f, a1 = 0.f, a2 = 0.f, a3 = 0.f;
        float b0 = 0.f, b1 = 0.f, b2 = 0.f, b3 = 0.f;

        #pragma unroll
        for (int p = 0; p < FAN_IN / 2; p++) {
            const uint4 tp = taps[p];   // {off0, w0, off1, w1} -> 2 taps per LDG.128

            unsigned wa = *reinterpret_cast<const unsigned*>(sp + tp.x + lb);
            float wtA = __int_as_float((int)tp.y);
            a0 = fmaf(wtA, u2f(wa, 0), a0);
            a1 = fmaf(wtA, u2f(wa, 1), a1);
            a2 = fmaf(wtA, u2f(wa, 2), a2);
            a3 = fmaf(wtA, u2f(wa, 3), a3);

            unsigned wb = *reinterpret_cast<const unsigned*>(sp + tp.z + lb);
            float wtB = __int_as_float((int)tp.w);
            b0 = fmaf(wtB, u2f(wb, 0), b0);
            b1 = fmaf(wtB, u2f(wb, 1), b1);
            b2 = fmaf(wtB, u2f(wb, 2), b2);
            b3 = fmaf(wtB, u2f(wb, 3), b3);
        }

        float4 res;
        res.x = fq_out(a0 + b0);
        res.y = fq_out(a1 + b1);
        res.z = fq_out(a2 + b2);
        res.w = fq_out(a3 + b3);
        __stcs(reinterpret_cast<float4*>(outn + (size_t)o * LEN + lb), res);
    }
}

extern "C" void kernel_launch(void* const* d_in, const int* in_sizes, int n_in,
                              void* d_out, int out_size) {
    const float* x      = (const float*)d_in[0];
    const float* weight = (const float*)d_in[1];
    const float* mask   = (const float*)d_in[2];
    float*       out    = (float*)d_out;

    prep_taps_kernel<<<OUT_CH, IN_CH * KW>>>(weight, mask);
    sparse_conv1d_kernel<<<BATCH * (LEN / TILE_T), NTHREADS>>>(x, out);
}

// round 11
// speedup vs baseline: 1.6798x; 1.6798x over previous
#include <cuda_runtime.h>
#include <cuda_fp16.h>

// SparseConv1dNeq: fake-quant(in) -> masked sparse conv1d (fan-in 8, pad 1) -> fake-quant(out)
// x [512,64,1024] f32, weight [64,64,3] f32, mask [64,64,3] f32, out [512,64,1024] f32
//
// int8 smem (3 shifted copies, 24KB) -> 1 LDS.32 per tap per 128 positions.
// Decode: PRMT magic (0x4B0000uu = 8388608+u) then PACKED f32x2 debias+FMA
// (add.rn.f32x2 / fma.rn.f32x2) -> half the fma-pipe instructions of scalar.
// Quant chain is exact: (x*16) exact FMUL, FRND ties-even, +128 exact, clamp 255,
// cvt.rni.u32 saturates negatives -> matches reference bit-for-bat pre-sum-order.
// IN_SCALE*OUT_SCALE_INV = 0.5 folded into one epilogue FMUL (weights unscaled).

#define BATCH   512
#define IN_CH   64
#define OUT_CH  64
#define KW      3
#define LEN     1024
#define FAN_IN  8
#define TILE_T  128
#define NTHREADS 256

#define ROW_B  128             // bytes per row per copy
#define A_BASE 0               // A[r][j] = x[t0+j]    (k=1)
#define B_BASE 8192            // B[r][j] = x[t0-1+j]  (k=0)
#define C_BASE 16384           // C[r][j] = x[t0+1+j]  (k=2)
#define SMEM_BYTES 24576

#define OUT_SCALE 0.125f

typedef unsigned long long ull;

// packed f32x2 helpers (Blackwell)
#define PACKF2(d, lo, hi)  asm("mov.b64 %0, {%1, %2};" : "=l"(d) : "f"(lo), "f"(hi))
#define UNPACKF2(lo, hi, s) asm("mov.b64 {%0, %1}, %2;" : "=f"(lo), "=f"(hi) : "l"(s))
#define ADD2(d, a, b)  asm("add.rn.f32x2 %0, %1, %2;" : "=l"(d) : "l"(a), "l"(b))
#define FMA2(d, a, b, c) asm("fma.rn.f32x2 %0, %1, %2, %3;" : "=l"(d) : "l"(a), "l"(b), "l"(c))

// -8388736.0f = -(2^23 + 128) ; bits 0xCB000080
#define DEBIAS2 0xCB000080CB000080ULL

// Packed taps: per out channel 4 x uint4 = {byteOff0, w0bits, byteOff1, w1bits}
__device__ uint4 g_tap[OUT_CH * FAN_IN / 2];

// ---------------- Prep: parallel ballot-based tap compaction ----------------
__global__ void prep_taps_kernel(const float* __restrict__ weight,
                                 const float* __restrict__ mask) {
    const int o   = blockIdx.x;
    const int idx = threadIdx.x;          // 0..191 over (ic*KW + k)
    __shared__ int wcnt[6];
    __shared__ int total;

    float m = mask[o * (IN_CH * KW) + idx];
    bool  p = (m != 0.0f);

    unsigned bal = __ballot_sync(0xffffffffu, p);
    int warp = idx >> 5;
    int lane = idx & 31;
    if (lane == 0) wcnt[warp] = __popc(bal);
    __syncthreads();

    int prefix = 0;
    #pragma unroll
    for (int w = 0; w < 6; w++)
        if (w < warp) prefix += wcnt[w];
    if (idx == 0) {
        int t = 0;
        #pragma unroll
        for (int w = 0; w < 6; w++) t += wcnt[w];
        total = t;
    }
    int rank = prefix + __popc(bal & ((1u << lane) - 1u));
    __syncthreads();

    int* gt = (int*)g_tap;
    if (p && rank < FAN_IN) {
        int ic = idx / KW;
        int k  = idx - ic * KW;
        int off;
        if (k == 0)      off = B_BASE + ic * ROW_B;
        else if (k == 1) off = A_BASE + ic * ROW_B;
        else             off = C_BASE + ic * ROW_B;
        gt[(o * FAN_IN + rank) * 2]     = off;
        gt[(o * FAN_IN + rank) * 2 + 1] = __float_as_int(weight[o * (IN_CH * KW) + idx] * m);
    }
    if (idx < FAN_IN && idx >= total) {
        gt[(o * FAN_IN + idx) * 2]     = 0;
        gt[(o * FAN_IN + idx) * 2 + 1] = 0;
    }
}

// exact biased quant to one byte: u = clip(rint(x*16), -128, 127) + 128
// x*16 is an exact FMUL (power of two); FRND ties-to-even == jnp.round;
// +128 exact on integral value; upper clamp FMNMX; cvt.rni.u32 saturates <0 to 0.
__device__ __forceinline__ unsigned qbyte(float x) {
    float f = rintf(x * 16.0f) + 128.0f;
    f = fminf(f, 255.0f);
    return __float2uint_rn(f);
}

// ---------------- Main kernel ----------------
__global__ __launch_bounds__(NTHREADS, 5)
void sparse_conv1d_kernel(const float* __restrict__ x,
                          float* __restrict__ out) {
    __shared__ __align__(16) char xs[SMEM_BYTES];
    char* sp = xs;

    const int blk  = blockIdx.x;
    const int n    = blk >> 3;
    const int tile = blk & 7;
    const int t0   = tile * TILE_T;

    const float* xn = x + (size_t)n * IN_CH * LEN;
    const int tid  = threadIdx.x;
    const int lane = tid & 31;
    const int warp = tid >> 5;

    // ---- Load: warp covers one row per iter (32 lanes x 4 positions) ----
    #pragma unroll
    for (int it = 0; it < 8; it++) {
        const int r = warp + it * 8;
        const float* rowg = xn + r * LEN;
        const float4 q = __ldcs(reinterpret_cast<const float4*>(rowg + t0 + (lane << 2)));

        unsigned u0 = qbyte(q.x), u1 = qbyte(q.y), u2 = qbyte(q.z), u3 = qbyte(q.w);
        unsigned t01 = __byte_perm(u0, u1, 0x0040);   // bytes (u0,u1,-,-)
        unsigned t23 = __byte_perm(u2, u3, 0x0040);
        unsigned w   = __byte_perm(t01, t23, 0x5410); // bytes (u0,u1,u2,u3)

        // halo: lane 0 -> x[t0-1], lane 31 -> x[t0+128] (biased-zero 128 when OOB)
        bool hl = (lane == 0)  && (t0 > 0);
        bool hr = (lane == 31) && (t0 + TILE_T < LEN);
        unsigned hu = 128u;
        if (hl) hu = qbyte(__ldcs(rowg + t0 - 1));
        if (hr) hu = qbyte(__ldcs(rowg + t0 + TILE_T));

        unsigned w_prev = __shfl_up_sync(0xffffffffu, w, 1);
        unsigned w_next = __shfl_down_sync(0xffffffffu, w, 1);
        if (lane == 0)  w_prev = hu << 24;   // byte3 = x[t0-1]
        if (lane == 31) w_next = hu;         // byte0 = x[t0+128]

        char* rp = sp + r * ROW_B + (lane << 2);
        *reinterpret_cast<unsigned*>(rp + A_BASE) = w;
        *reinterpret_cast<unsigned*>(rp + B_BASE) = __byte_perm(w, w_prev, 0x2107);
        *reinterpret_cast<unsigned*>(rp + C_BASE) = __byte_perm(w, w_next, 0x4321);
    }
    __syncthreads();

    // ---- Compute: warp w -> out channels [w*8, w*8+8); lane -> positions 4l..4l+3 ----
    float* outn = out + (size_t)n * OUT_CH * LEN + t0;
    const int lb = lane << 2;

    #pragma unroll 1
    for (int oi = 0; oi < 8; oi++) {
        const int o = warp * 8 + oi;
        const uint4* taps = g_tap + o * (FAN_IN / 2);

        ull accA01 = 0ULL, accA23 = 0ULL;   // packed (0.0f, 0.0f)
        ull accB01 = 0ULL, accB23 = 0ULL;

        #pragma unroll
        for (int p = 0; p < FAN_IN / 2; p++) {
            const uint4 tp = taps[p];   // {off0, w0, off1, w1} -> 2 taps per LDG.128

            // tap A
            {
                unsigned wa = *reinterpret_cast<const unsigned*>(sp + tp.x + lb);
                float wf = __int_as_float((int)tp.y);
                ull ww; PACKF2(ww, wf, wf);
                unsigned r0 = __byte_perm(wa, 0x4B000000u, 0x7650u);
                unsigned r1 = __byte_perm(wa, 0x4B000000u, 0x7651u);
                unsigned r2 = __byte_perm(wa, 0x4B000000u, 0x7652u);
                unsigned r3 = __byte_perm(wa, 0x4B000000u, 0x7653u);
                ull p01, p23;
                asm("mov.b64 %0, {%1, %2};" : "=l"(p01) : "r"(r0), "r"(r1));
                asm("mov.b64 %0, {%1, %2};" : "=l"(p23) : "r"(r2), "r"(r3));
                ull q01, q23;
                ADD2(q01, p01, DEBIAS2);    // exact: (8388608+u) - 8388736 = q
                ADD2(q23, p23, DEBIAS2);
                FMA2(accA01, ww, q01, accA01);
                FMA2(accA23, ww, q23, accA23);
            }
            // tap B
            {
                unsigned wb = *reinterpret_cast<const unsigned*>(sp + tp.z + lb);
                float wf = __int_as_float((int)tp.w);
                ull ww; PACKF2(ww, wf, wf);
                unsigned r0 = __byte_perm(wb, 0x4B000000u, 0x7650u);
                unsigned r1 = __byte_perm(wb, 0x4B000000u, 0x7651u);
                unsigned r2 = __byte_perm(wb, 0x4B000000u, 0x7652u);
                unsigned r3 = __byte_perm(wb, 0x4B000000u, 0x7653u);
                ull p01, p23;
                asm("mov.b64 %0, {%1, %2};" : "=l"(p01) : "r"(r0), "r"(r1));
                asm("mov.b64 %0, {%1, %2};" : "=l"(p23) : "r"(r2), "r"(r3));
                ull q01, q23;
                ADD2(q01, p01, DEBIAS2);
                ADD2(q23, p23, DEBIAS2);
                FMA2(accB01, ww, q01, accB01);
                FMA2(accB23, ww, q23, accB23);
            }
        }

        ull s01, s23;
        ADD2(s01, accA01, accB01);
        ADD2(s23, accA23, accB23);
        float v0, v1, v2, v3;
        UNPACKF2(v0, v1, s01);
        UNPACKF2(v2, v3, s23);

        // out = clip(rint(v * (IN_SCALE*8)), -128, 127) * 0.125 ; 0.5*v exact FMUL
        float4 res;
        {
            float t;
            t = rintf(v0 * 0.5f); t = fminf(fmaxf(t, -128.0f), 127.0f); res.x = t * OUT_SCALE;
            t = rintf(v1 * 0.5f); t = fminf(fmaxf(t, -128.0f), 127.0f); res.y = t * OUT_SCALE;
            t = rintf(v2 * 0.5f); t = fminf(fmaxf(t, -128.0f), 127.0f); res.z = t * OUT_SCALE;
            t = rintf(v3 * 0.5f); t = fminf(fmaxf(t, -128.0f), 127.0f); res.w = t * OUT_SCALE;
        }
        __stcs(reinterpret_cast<float4*>(outn + (size_t)o * LEN + lb), res);
    }
}

extern "C" void kernel_launch(void* const* d_in, const int* in_sizes, int n_in,
                              void* d_out, int out_size) {
    const float* x      = (const float*)d_in[0];
    const float* weight = (const float*)d_in[1];
    const float* mask   = (const float*)d_in[2];
    float*       out    = (float*)d_out;

    prep_taps_kernel<<<OUT_CH, IN_CH * KW>>>(weight, mask);
    sparse_conv1d_kernel<<<BATCH * (LEN / TILE_T), NTHREADS>>>(x, out);
}